// round 1
// baseline (speedup 1.0000x reference)
#include <cuda_runtime.h>
#include <cuda_bf16.h>
#include <cstdint>

// ---------------- problem constants ----------------
#define KP    320          // padded K (HIDDEN=300 -> 320) ; also padded row length of h buffers
#define BM    128
#define BN    128
#define BK    32
#define BKP   40           // padded smem stride (conflict-free)
#define MAX_EDGES 1000000

// ---------------- device scratch (static, no allocs) ----------------
__device__ __align__(16) __nv_bfloat16 g_h1[(size_t)MAX_EDGES * KP];   // ~610 MB
__device__ __align__(16) __nv_bfloat16 g_h2[(size_t)MAX_EDGES * KP];   // ~610 MB
__device__ __align__(16) __nv_bfloat16 g_W2t[384 * KP];                // W2^T padded [N=384][K=320]
__device__ __align__(16) __nv_bfloat16 g_W3t[256 * KP];                // W3^T padded [N=256][K=320]
__device__ double g_acc[2];   // [0]=sum|y-t|, [1]=KL sum

// ---------------- small helpers ----------------
__device__ __forceinline__ uint32_t smem_u32(const void* p) {
    return (uint32_t)__cvta_generic_to_shared(p);
}

// ---------------- kernel: zero accumulators ----------------
__global__ void k_zero() {
    g_acc[0] = 0.0;
    g_acc[1] = 0.0;
}

// ---------------- kernel: base MAE reduction ----------------
__global__ void k_base(const float* __restrict__ y, const float* __restrict__ tg, int n) {
    __shared__ float red[8];
    float local = 0.f;
    for (int i = blockIdx.x * blockDim.x + threadIdx.x; i < n; i += gridDim.x * blockDim.x)
        local += fabsf(y[i] - tg[i]);
    int lane = threadIdx.x & 31, warp = threadIdx.x >> 5;
    #pragma unroll
    for (int o = 16; o > 0; o >>= 1) local += __shfl_xor_sync(0xffffffffu, local, o);
    if (lane == 0) red[warp] = local;
    __syncthreads();
    if (threadIdx.x < 8) {
        float v = red[threadIdx.x];
        #pragma unroll
        for (int o = 4; o > 0; o >>= 1) v += __shfl_xor_sync(0xffu, v, o);
        if (threadIdx.x == 0) atomicAdd(&g_acc[0], (double)v);
    }
}

// ---------------- kernel: weight prep (transpose+pad+convert to bf16) ----------------
// W2: [300][300] row-major fp32 -> g_W2t[n][k] = W2[k][n], zero-padded to [384][320]
// W3: [300][200] row-major fp32 -> g_W3t[n][k] = W3[k][n], zero-padded to [256][320]
__global__ void k_prep_w(const float* __restrict__ W2, const float* __restrict__ W3) {
    int i = blockIdx.x * blockDim.x + threadIdx.x;
    if (i < 384 * KP) {
        int n = i / KP, k = i % KP;
        float v = (n < 300 && k < 300) ? W2[k * 300 + n] : 0.f;
        g_W2t[i] = __float2bfloat16(v);
    }
    if (i < 256 * KP) {
        int n = i / KP, k = i % KP;
        float v = (n < 200 && k < 300) ? W3[k * 200 + n] : 0.f;
        g_W3t[i] = __float2bfloat16(v);
    }
}

// ---------------- kernel 1: gather + GEMM1 + ReLU -> h1 (bf16, padded) ----------------
__global__ void k1_gather_gemm1(const float* __restrict__ x,
                                const int*   __restrict__ ei,
                                const float* __restrict__ W1,
                                const float* __restrict__ b1,
                                int nEdges) {
    __shared__ float W1s[12 * 300];
    __shared__ float b1s[300];
    __shared__ float Es[64][12];
    const int t = threadIdx.x;
    for (int i = t; i < 3600; i += 256) W1s[i] = W1[i];
    for (int i = t; i < 300;  i += 256) b1s[i] = b1[i];
    const int eb = blockIdx.x * 64;
    if (t < 128) {
        int el = t >> 1, w = t & 1;
        int e = eb + el;
        if (e < nEdges) {
            int node = ei[(size_t)w * nEdges + e];
            #pragma unroll
            for (int k = 0; k < 6; k++) Es[el][w * 6 + k] = x[(size_t)node * 6 + k];
        }
    }
    __syncthreads();
    for (int idx = t; idx < 64 * KP; idx += 256) {
        int el = idx / KP, j = idx % KP;
        int e = eb + el;
        if (e >= nEdges) break;
        float h = 0.f;
        if (j < 300) {
            float s = b1s[j];
            #pragma unroll
            for (int k = 0; k < 12; k++) s += Es[el][k] * W1s[k * 300 + j];
            h = fmaxf(s, 0.f);
        }
        g_h1[(size_t)e * KP + j] = __float2bfloat16(h);
    }
}

// ---------------- fused tiled bf16 GEMM (mma.sync) ----------------
// MODE 2: C = relu(A@W2 + b2) -> g_h2  (BIASN = 300)
// MODE 3: KL epilogue over messages = A@W3 + b3, accumulate into g_acc[1] (BIASN = 200)
template<int MODE, int BIASN>
__global__ __launch_bounds__(256, 2)
void gemm_fused(const float* __restrict__ bias, int M) {
    __shared__ alignas(16) __nv_bfloat16 As[2][BM][BKP];
    __shared__ alignas(16) __nv_bfloat16 Bs[2][BN][BKP];
    __shared__ float red[8];

    const __nv_bfloat16* __restrict__ A  = (MODE == 2) ? g_h1  : g_h2;
    const __nv_bfloat16* __restrict__ Bt = (MODE == 2) ? g_W2t : g_W3t;

    const int t = threadIdx.x;
    const int lane = t & 31, warp = t >> 5;
    const int mBase = blockIdx.x * BM;
    const int nBase = blockIdx.y * BN;
    const int wm = (warp >> 2) * 64;     // 2 warp-rows of 64
    const int wn = (warp & 3) * 32;      // 4 warp-cols of 32

    auto load_tile = [&](int s, int kc) {
        const int k0 = kc * BK;
        #pragma unroll
        for (int i = 0; i < 2; i++) {
            int v = t + i * 256;
            int row = v >> 2;
            int c8 = (v & 3) << 3;
            int gr = mBase + row;
            bool ok = gr < M;
            const __nv_bfloat16* gA = A + (size_t)(ok ? gr : 0) * KP + k0 + c8;
            uint32_t sA = smem_u32(&As[s][row][c8]);
            int sz = ok ? 16 : 0;
            asm volatile("cp.async.cg.shared.global [%0], [%1], 16, %2;\n"
                         :: "r"(sA), "l"(gA), "r"(sz));
            const __nv_bfloat16* gB = Bt + (size_t)(nBase + row) * KP + k0 + c8;
            uint32_t sB = smem_u32(&Bs[s][row][c8]);
            asm volatile("cp.async.cg.shared.global [%0], [%1], 16;\n"
                         :: "r"(sB), "l"(gB));
        }
    };

    float acc[4][4][4];
    #pragma unroll
    for (int i = 0; i < 4; i++)
        #pragma unroll
        for (int j = 0; j < 4; j++)
            #pragma unroll
            for (int k = 0; k < 4; k++) acc[i][j][k] = 0.f;

    constexpr int NK = KP / BK;   // 10
    load_tile(0, 0);
    asm volatile("cp.async.commit_group;\n");
    int s = 0;
    for (int kc = 0; kc < NK; kc++) {
        if (kc + 1 < NK) load_tile(s ^ 1, kc + 1);
        asm volatile("cp.async.commit_group;\n");
        asm volatile("cp.async.wait_group 1;\n");
        __syncthreads();
        #pragma unroll
        for (int kk = 0; kk < 2; kk++) {
            uint32_t a[4][4], b[4][2];
            int arow = wm + (lane & 15);
            int acol = kk * 16 + (lane >> 4) * 8;
            #pragma unroll
            for (int mi = 0; mi < 4; mi++)
                asm volatile("ldmatrix.sync.aligned.m8n8.x4.shared.b16 {%0,%1,%2,%3}, [%4];\n"
                    : "=r"(a[mi][0]), "=r"(a[mi][1]), "=r"(a[mi][2]), "=r"(a[mi][3])
                    : "r"(smem_u32(&As[s][arow + mi * 16][acol])));
            int brow = wn + (lane & 7);
            int bcol = kk * 16 + ((lane >> 3) & 1) * 8;
            #pragma unroll
            for (int ni = 0; ni < 4; ni++)
                asm volatile("ldmatrix.sync.aligned.m8n8.x2.shared.b16 {%0,%1}, [%2];\n"
                    : "=r"(b[ni][0]), "=r"(b[ni][1])
                    : "r"(smem_u32(&Bs[s][brow + ni * 8][bcol])));
            #pragma unroll
            for (int mi = 0; mi < 4; mi++)
                #pragma unroll
                for (int ni = 0; ni < 4; ni++)
                    asm volatile("mma.sync.aligned.m16n8k16.row.col.f32.bf16.bf16.f32 "
                        "{%0,%1,%2,%3}, {%4,%5,%6,%7}, {%8,%9}, {%0,%1,%2,%3};\n"
                        : "+f"(acc[mi][ni][0]), "+f"(acc[mi][ni][1]),
                          "+f"(acc[mi][ni][2]), "+f"(acc[mi][ni][3])
                        : "r"(a[mi][0]), "r"(a[mi][1]), "r"(a[mi][2]), "r"(a[mi][3]),
                          "r"(b[ni][0]), "r"(b[ni][1]));
        }
        __syncthreads();
        s ^= 1;
    }

    const int g = lane >> 2, q = lane & 3;
    if (MODE == 2) {
        #pragma unroll
        for (int mi = 0; mi < 4; mi++) {
            #pragma unroll
            for (int ni = 0; ni < 4; ni++) {
                int c0 = nBase + wn + ni * 8 + q * 2;
                if (c0 >= KP) continue;
                float b0 = (c0     < BIASN) ? bias[c0]     : 0.f;
                float b1v = (c0 + 1 < BIASN) ? bias[c0 + 1] : 0.f;
                int r0 = mBase + wm + mi * 16 + g;
                if (r0 < M) {
                    __nv_bfloat162 v = __floats2bfloat162_rn(
                        fmaxf(acc[mi][ni][0] + b0, 0.f),
                        fmaxf(acc[mi][ni][1] + b1v, 0.f));
                    *(__nv_bfloat162*)&g_h2[(size_t)r0 * KP + c0] = v;
                }
                if (r0 + 8 < M) {
                    __nv_bfloat162 v = __floats2bfloat162_rn(
                        fmaxf(acc[mi][ni][2] + b0, 0.f),
                        fmaxf(acc[mi][ni][3] + b1v, 0.f));
                    *(__nv_bfloat162*)&g_h2[(size_t)(r0 + 8) * KP + c0] = v;
                }
            }
        }
    } else {
        float local = 0.f;
        #pragma unroll
        for (int mi = 0; mi < 4; mi++) {
            #pragma unroll
            for (int ni = 0; ni < 4; ni++) {
                int c0 = nBase + wn + ni * 8 + q * 2;
                int r0 = mBase + wm + mi * 16 + g;
                #pragma unroll
                for (int h = 0; h < 2; h++) {
                    int r = r0 + h * 8;
                    if (r >= M) continue;
                    #pragma unroll
                    for (int j = 0; j < 2; j++) {
                        int c = c0 + j;
                        if (c >= 200) continue;
                        float v = acc[mi][ni][h * 2 + j] + bias[c];
                        local += (c < 100) ? 0.5f * v * v
                                           : 0.5f * (__expf(v) - v - 1.f);
                    }
                }
            }
        }
        #pragma unroll
        for (int o = 16; o > 0; o >>= 1) local += __shfl_xor_sync(0xffffffffu, local, o);
        if (lane == 0) red[warp] = local;
        __syncthreads();
        if (t < 8) {
            float v = red[t];
            #pragma unroll
            for (int o = 4; o > 0; o >>= 1) v += __shfl_xor_sync(0xffu, v, o);
            if (t == 0) atomicAdd(&g_acc[1], (double)v);
        }
    }
}

// ---------------- finalize ----------------
__global__ void k_finalize(float* out, int nNodes, int nEdges) {
    out[0] = (float)(g_acc[0] / (double)nNodes + g_acc[1] / (double)nEdges);
}

// ---------------- launch ----------------
extern "C" void kernel_launch(void* const* d_in, const int* in_sizes, int n_in,
                              void* d_out, int out_size) {
    const float* x   = (const float*)d_in[0];
    const int*   ei  = (const int*)  d_in[1];
    const float* y   = (const float*)d_in[2];
    const float* tgt = (const float*)d_in[3];
    const float* W1  = (const float*)d_in[4];
    const float* b1  = (const float*)d_in[5];
    const float* W2  = (const float*)d_in[6];
    const float* b2  = (const float*)d_in[7];
    const float* W3  = (const float*)d_in[8];
    const float* b3  = (const float*)d_in[9];
    float* out = (float*)d_out;

    const int nNodes = in_sizes[0] / 6;
    const int nEdges = in_sizes[1] / 2;
    const int nY     = in_sizes[2];

    k_zero<<<1, 1>>>();
    k_base<<<128, 256>>>(y, tgt, nY);
    k_prep_w<<<(384 * KP + 255) / 256, 256>>>(W2, W3);
    k1_gather_gemm1<<<(nEdges + 63) / 64, 256>>>(x, ei, W1, b1, nEdges);

    const int mBlocks = (nEdges + BM - 1) / BM;
    gemm_fused<2, 300><<<dim3(mBlocks, 3), 256>>>(b2, nEdges);   // h2 = relu(h1@W2+b2)
    gemm_fused<3, 200><<<dim3(mBlocks, 2), 256>>>(b3, nEdges);   // KL over h2@W3+b3

    k_finalize<<<1, 1>>>(out, nNodes, nEdges);
}

// round 2
// speedup vs baseline: 1.3612x; 1.3612x over previous
#include <cuda_runtime.h>
#include <cuda_bf16.h>
#include <cstdint>

// ---------------- constants ----------------
#define KP   320           // padded weight K / hidden width (300 -> 320)
#define SH   328           // smem row stride (elems) for H1/H2 tiles (conflict-free ldmatrix)
#define BM   128           // edges per block
#define BSTR 40            // Bs smem row stride (elems)

// ---------------- device scratch (weights only; h buffers live in smem now) ----------------
__device__ __align__(16) __nv_bfloat16 g_W1t[384 * 16];   // W1^T padded [n=384][k=16]
__device__ __align__(16) __nv_bfloat16 g_W2t[384 * KP];   // W2^T padded [n=384][k=320]
__device__ __align__(16) __nv_bfloat16 g_W3t[256 * KP];   // W3^T padded [n=256][k=320]
__device__ double g_acc[2];                               // [0]=sum|y-t|, [1]=KL sum

__device__ __forceinline__ uint32_t smem_u32(const void* p) {
    return (uint32_t)__cvta_generic_to_shared(p);
}

// ---------------- zero accumulators ----------------
__global__ void k_zero() { g_acc[0] = 0.0; g_acc[1] = 0.0; }

// ---------------- base MAE reduction ----------------
__global__ void k_base(const float* __restrict__ y, const float* __restrict__ tg, int n) {
    __shared__ float red[8];
    float local = 0.f;
    for (int i = blockIdx.x * blockDim.x + threadIdx.x; i < n; i += gridDim.x * blockDim.x)
        local += fabsf(y[i] - tg[i]);
    int lane = threadIdx.x & 31, warp = threadIdx.x >> 5;
    #pragma unroll
    for (int o = 16; o > 0; o >>= 1) local += __shfl_xor_sync(0xffffffffu, local, o);
    if (lane == 0) red[warp] = local;
    __syncthreads();
    if (threadIdx.x < 8) {
        float v = red[threadIdx.x];
        #pragma unroll
        for (int o = 4; o > 0; o >>= 1) v += __shfl_xor_sync(0xffu, v, o);
        if (threadIdx.x == 0) atomicAdd(&g_acc[0], (double)v);
    }
}

// ---------------- weight prep: transpose + pad + bf16 ----------------
__global__ void k_prep_w(const float* __restrict__ W1,
                         const float* __restrict__ W2,
                         const float* __restrict__ W3) {
    int i = blockIdx.x * blockDim.x + threadIdx.x;
    if (i < 384 * 16) {
        int n = i / 16, k = i % 16;
        g_W1t[i] = __float2bfloat16((n < 300 && k < 12) ? W1[k * 300 + n] : 0.f);
    }
    if (i < 384 * KP) {
        int n = i / KP, k = i % KP;
        g_W2t[i] = __float2bfloat16((n < 300 && k < 300) ? W2[k * 300 + n] : 0.f);
    }
    if (i < 256 * KP) {
        int n = i / KP, k = i % KP;
        g_W3t[i] = __float2bfloat16((n < 200 && k < 300) ? W3[k * 200 + n] : 0.f);
    }
}

// ---------------- fully fused edge pipeline ----------------
// smem layout (dynamic):
//   H1  : [128][SH] bf16      83968 B
//   H2  : [128][SH] bf16      83968 B
//   Bs  : [2][128][BSTR] bf16 20480 B
//   W1s : [384][16] bf16      12288 B
//   Es  : [128][16] bf16       4096 B
//   b1s : 320 f32, b2s : 320 f32, b3s : 256 f32, red : 8 f32
#define SMEM_BYTES (83968 + 83968 + 20480 + 12288 + 4096 + 320*4 + 320*4 + 256*4 + 32)

__global__ __launch_bounds__(256, 1)
void k_fused(const float* __restrict__ x,
             const int*   __restrict__ ei,
             const float* __restrict__ b1,
             const float* __restrict__ b2,
             const float* __restrict__ b3,
             int nEdges) {
    extern __shared__ __align__(16) char smem_raw[];
    __nv_bfloat16* H1  = (__nv_bfloat16*)smem_raw;
    __nv_bfloat16* H2  = H1 + 128 * SH;
    __nv_bfloat16* Bs  = H2 + 128 * SH;
    __nv_bfloat16* W1s = Bs + 2 * 128 * BSTR;
    __nv_bfloat16* Es  = W1s + 384 * 16;
    float* b1s = (float*)(Es + 128 * 16);
    float* b2s = b1s + 320;
    float* b3s = b2s + 320;
    float* red = b3s + 256;

    const int t = threadIdx.x;
    const int lane = t & 31, warp = t >> 5;
    const int mBase = blockIdx.x * BM;
    const int wm = (warp >> 2) * 64;
    const int wn = (warp & 3) * 32;
    const int g = lane >> 2, q = lane & 3;

    // ---- stage 0: load weights/bias/edge features into smem ----
    {
        const uint4* src = (const uint4*)g_W1t;
        uint4* dst = (uint4*)W1s;
        for (int i = t; i < 384 * 16 * 2 / 16; i += 256) dst[i] = src[i];
    }
    for (int i = t; i < 320; i += 256) {
        b1s[i] = (i < 300) ? b1[i] : 0.f;
        b2s[i] = (i < 300) ? b2[i] : 0.f;
    }
    if (t < 256) b3s[t] = (t < 200) ? b3[t] : 0.f;
    {
        int el = t >> 1, half = t & 1;
        int e = mBase + el;
        __nv_bfloat16* row = Es + el * 16 + half * 6;
        float v[6] = {0.f, 0.f, 0.f, 0.f, 0.f, 0.f};
        if (e < nEdges) {
            int node = ei[half ? (size_t)nEdges + e : (size_t)e];
            const float* xp = x + (size_t)node * 6;
            float2 a0 = *(const float2*)xp;
            float2 a1 = *(const float2*)(xp + 2);
            float2 a2 = *(const float2*)(xp + 4);
            v[0] = a0.x; v[1] = a0.y; v[2] = a1.x; v[3] = a1.y; v[4] = a2.x; v[5] = a2.y;
        }
        #pragma unroll
        for (int k = 0; k < 6; k++) row[k] = __float2bfloat16(v[k]);
        if (half) {  // zero K-pad cols 12..15
            *(__nv_bfloat162*)(Es + el * 16 + 12) = __floats2bfloat162_rn(0.f, 0.f);
            *(__nv_bfloat162*)(Es + el * 16 + 14) = __floats2bfloat162_rn(0.f, 0.f);
        }
    }
    __syncthreads();

    float acc[4][4][4];

    // ---- stage 1: GEMM1 (Es[128x16] @ W1t -> H1), 3 n-passes ----
    {
        uint32_t a[4][4];
        const int arow = wm + (lane & 15);
        const int acol = (lane >> 4) * 8;
        #pragma unroll
        for (int mi = 0; mi < 4; mi++)
            asm volatile("ldmatrix.sync.aligned.m8n8.x4.shared.b16 {%0,%1,%2,%3}, [%4];\n"
                : "=r"(a[mi][0]), "=r"(a[mi][1]), "=r"(a[mi][2]), "=r"(a[mi][3])
                : "r"(smem_u32(Es + (arow + mi * 16) * 16 + acol)));
        #pragma unroll
        for (int p = 0; p < 3; p++) {
            const int n0 = p * 128;
            #pragma unroll
            for (int mi = 0; mi < 4; mi++)
                #pragma unroll
                for (int ni = 0; ni < 4; ni++)
                    #pragma unroll
                    for (int r = 0; r < 4; r++) acc[mi][ni][r] = 0.f;
            uint32_t b[4][2];
            const int brow = n0 + wn + (lane & 7);
            const int bcol = ((lane >> 3) & 1) * 8;
            #pragma unroll
            for (int ni = 0; ni < 4; ni++)
                asm volatile("ldmatrix.sync.aligned.m8n8.x2.shared.b16 {%0,%1}, [%2];\n"
                    : "=r"(b[ni][0]), "=r"(b[ni][1])
                    : "r"(smem_u32(W1s + (brow + ni * 8) * 16 + bcol)));
            #pragma unroll
            for (int mi = 0; mi < 4; mi++)
                #pragma unroll
                for (int ni = 0; ni < 4; ni++)
                    asm volatile("mma.sync.aligned.m16n8k16.row.col.f32.bf16.bf16.f32 "
                        "{%0,%1,%2,%3}, {%4,%5,%6,%7}, {%8,%9}, {%0,%1,%2,%3};\n"
                        : "+f"(acc[mi][ni][0]), "+f"(acc[mi][ni][1]),
                          "+f"(acc[mi][ni][2]), "+f"(acc[mi][ni][3])
                        : "r"(a[mi][0]), "r"(a[mi][1]), "r"(a[mi][2]), "r"(a[mi][3]),
                          "r"(b[ni][0]), "r"(b[ni][1]));
            // epilogue: relu(+b1) -> H1 smem
            #pragma unroll
            for (int mi = 0; mi < 4; mi++)
                #pragma unroll
                for (int ni = 0; ni < 4; ni++) {
                    int c0 = n0 + wn + ni * 8 + q * 2;
                    if (c0 >= 320) continue;
                    float bb0 = b1s[c0], bb1 = b1s[c0 + 1];
                    int r0 = wm + mi * 16 + g;
                    *(__nv_bfloat162*)(H1 + r0 * SH + c0) = __floats2bfloat162_rn(
                        fmaxf(acc[mi][ni][0] + bb0, 0.f), fmaxf(acc[mi][ni][1] + bb1, 0.f));
                    *(__nv_bfloat162*)(H1 + (r0 + 8) * SH + c0) = __floats2bfloat162_rn(
                        fmaxf(acc[mi][ni][2] + bb0, 0.f), fmaxf(acc[mi][ni][3] + bb1, 0.f));
                }
        }
    }

    // ---- shared K-loop: acc += Asm[128xKP] @ Bg[n0..n0+127][KP] ----
    auto kloop = [&](const __nv_bfloat16* Asm, const __nv_bfloat16* Bg) {
        #pragma unroll
        for (int mi = 0; mi < 4; mi++)
            #pragma unroll
            for (int ni = 0; ni < 4; ni++)
                #pragma unroll
                for (int r = 0; r < 4; r++) acc[mi][ni][r] = 0.f;
        auto loadB = [&](int buf, int kc) {
            #pragma unroll
            for (int i = 0; i < 2; i++) {
                int c = t + i * 256;
                int row = c >> 2, c8 = (c & 3) << 3;
                const __nv_bfloat16* src = Bg + (size_t)row * KP + kc * 32 + c8;
                uint32_t dst = smem_u32(Bs + buf * (128 * BSTR) + row * BSTR + c8);
                asm volatile("cp.async.cg.shared.global [%0], [%1], 16;\n"
                             :: "r"(dst), "l"(src));
            }
        };
        loadB(0, 0);
        asm volatile("cp.async.commit_group;\n");
        int s = 0;
        for (int kc = 0; kc < 10; kc++) {
            if (kc + 1 < 10) loadB(s ^ 1, kc + 1);
            asm volatile("cp.async.commit_group;\n");
            asm volatile("cp.async.wait_group 1;\n");
            __syncthreads();
            #pragma unroll
            for (int kk = 0; kk < 2; kk++) {
                uint32_t a[4][4], b[4][2];
                const int arow = wm + (lane & 15);
                const int acol = kc * 32 + kk * 16 + (lane >> 4) * 8;
                #pragma unroll
                for (int mi = 0; mi < 4; mi++)
                    asm volatile("ldmatrix.sync.aligned.m8n8.x4.shared.b16 {%0,%1,%2,%3}, [%4];\n"
                        : "=r"(a[mi][0]), "=r"(a[mi][1]), "=r"(a[mi][2]), "=r"(a[mi][3])
                        : "r"(smem_u32(Asm + (arow + mi * 16) * SH + acol)));
                const int brow = wn + (lane & 7);
                const int bcol = kk * 16 + ((lane >> 3) & 1) * 8;
                #pragma unroll
                for (int ni = 0; ni < 4; ni++)
                    asm volatile("ldmatrix.sync.aligned.m8n8.x2.shared.b16 {%0,%1}, [%2];\n"
                        : "=r"(b[ni][0]), "=r"(b[ni][1])
                        : "r"(smem_u32(Bs + s * (128 * BSTR) + (brow + ni * 8) * BSTR + bcol)));
                #pragma unroll
                for (int mi = 0; mi < 4; mi++)
                    #pragma unroll
                    for (int ni = 0; ni < 4; ni++)
                        asm volatile("mma.sync.aligned.m16n8k16.row.col.f32.bf16.bf16.f32 "
                            "{%0,%1,%2,%3}, {%4,%5,%6,%7}, {%8,%9}, {%0,%1,%2,%3};\n"
                            : "+f"(acc[mi][ni][0]), "+f"(acc[mi][ni][1]),
                              "+f"(acc[mi][ni][2]), "+f"(acc[mi][ni][3])
                            : "r"(a[mi][0]), "r"(a[mi][1]), "r"(a[mi][2]), "r"(a[mi][3]),
                              "r"(b[ni][0]), "r"(b[ni][1]));
            }
            __syncthreads();
            s ^= 1;
        }
    };

    // ---- stage 2: GEMM2 (H1 @ W2t -> H2), 3 n-passes ----
    #pragma unroll 1
    for (int p = 0; p < 3; p++) {
        const int n0 = p * 128;
        kloop(H1, g_W2t + (size_t)n0 * KP);
        #pragma unroll
        for (int mi = 0; mi < 4; mi++)
            #pragma unroll
            for (int ni = 0; ni < 4; ni++) {
                int c0 = n0 + wn + ni * 8 + q * 2;
                if (c0 >= 320) continue;
                float bb0 = b2s[c0], bb1 = b2s[c0 + 1];
                int r0 = wm + mi * 16 + g;
                *(__nv_bfloat162*)(H2 + r0 * SH + c0) = __floats2bfloat162_rn(
                    fmaxf(acc[mi][ni][0] + bb0, 0.f), fmaxf(acc[mi][ni][1] + bb1, 0.f));
                *(__nv_bfloat162*)(H2 + (r0 + 8) * SH + c0) = __floats2bfloat162_rn(
                    fmaxf(acc[mi][ni][2] + bb0, 0.f), fmaxf(acc[mi][ni][3] + bb1, 0.f));
            }
    }

    // ---- stage 3: GEMM3 (H2 @ W3t), fused KL epilogue, 2 n-passes ----
    float localKL = 0.f;
    #pragma unroll 1
    for (int p = 0; p < 2; p++) {
        const int n0 = p * 128;
        kloop(H2, g_W3t + (size_t)n0 * KP);
        #pragma unroll
        for (int mi = 0; mi < 4; mi++)
            #pragma unroll
            for (int ni = 0; ni < 4; ni++) {
                int c0 = n0 + wn + ni * 8 + q * 2;
                int r0 = mBase + wm + mi * 16 + g;
                #pragma unroll
                for (int h = 0; h < 2; h++) {
                    int r = r0 + h * 8;
                    if (r >= nEdges) continue;
                    #pragma unroll
                    for (int j = 0; j < 2; j++) {
                        int c = c0 + j;
                        if (c >= 200) continue;
                        float v = acc[mi][ni][h * 2 + j] + b3s[c];
                        localKL += (c < 100) ? 0.5f * v * v
                                             : 0.5f * (__expf(v) - v - 1.f);
                    }
                }
            }
    }

    // ---- block reduce + atomic ----
    #pragma unroll
    for (int o = 16; o > 0; o >>= 1) localKL += __shfl_xor_sync(0xffffffffu, localKL, o);
    if (lane == 0) red[warp] = localKL;
    __syncthreads();
    if (t < 8) {
        float v = red[t];
        #pragma unroll
        for (int o = 4; o > 0; o >>= 1) v += __shfl_xor_sync(0xffu, v, o);
        if (t == 0) atomicAdd(&g_acc[1], (double)v);
    }
}

// ---------------- finalize ----------------
__global__ void k_finalize(float* out, int nNodes, int nEdges) {
    out[0] = (float)(g_acc[0] / (double)nNodes + g_acc[1] / (double)nEdges);
}

// ---------------- launch ----------------
extern "C" void kernel_launch(void* const* d_in, const int* in_sizes, int n_in,
                              void* d_out, int out_size) {
    const float* x   = (const float*)d_in[0];
    const int*   ei  = (const int*)  d_in[1];
    const float* y   = (const float*)d_in[2];
    const float* tgt = (const float*)d_in[3];
    const float* W1  = (const float*)d_in[4];
    const float* b1  = (const float*)d_in[5];
    const float* W2  = (const float*)d_in[6];
    const float* b2  = (const float*)d_in[7];
    const float* W3  = (const float*)d_in[8];
    const float* b3  = (const float*)d_in[9];
    float* out = (float*)d_out;

    const int nNodes = in_sizes[0] / 6;
    const int nEdges = in_sizes[1] / 2;
    const int nY     = in_sizes[2];

    cudaFuncSetAttribute(k_fused, cudaFuncAttributeMaxDynamicSharedMemorySize, SMEM_BYTES);

    k_zero<<<1, 1>>>();
    k_base<<<128, 256>>>(y, tgt, nY);
    k_prep_w<<<(384 * KP + 255) / 256, 256>>>(W1, W2, W3);
    k_fused<<<(nEdges + BM - 1) / BM, 256, SMEM_BYTES>>>(x, ei, b1, b2, b3, nEdges);
    k_finalize<<<1, 1>>>(out, nNodes, nEdges);
}